// round 15
// baseline (speedup 1.0000x reference)
#include <cuda_runtime.h>
#include <cuda_bf16.h>

// 3x3 median blur, zero padding, 48 planes of 512x512 fp32.
// R13: R8's exact median network (17.5 min/max ops/output), fed from a
// shared-memory slab (R12 fixed): block stages 10 rows x (512+pads) with 5
// coalesced LDG.128/thread; per-row reads are ALIGNED LDS.128 + LDS.128 +
// LDS.32 via the layout [0..2 unused][3]=leftpad [4..515]=data [516]=rightpad,
// row stride 520 floats (16B-multiple). No halo branches, no strided LDGs.

constexpr int W  = 512;
constexpr int H  = 512;
constexpr int SW = 520;   // row stride in floats; 520*4 = 2080 B, 16B-multiple

__device__ __forceinline__ float med3f(float a, float b, float c) {
    return fmaxf(fminf(a, b), fminf(fmaxf(a, b), c));
}

// One output row: insert row r into the sorted pair (a<=b), then merge the
// 4 overlapping column-triples with shared pairwise extremes.
__device__ __forceinline__ void window_ins_store(
    const float a[6], const float b[6], const float r[6],
    float* __restrict__ q)
{
    float lo[6], mi[6], hi[6];
    #pragma unroll
    for (int i = 0; i < 6; i++) {
        const float mbr = fminf(b[i], r[i]);
        lo[i] = fminf(a[i], r[i]);
        mi[i] = fmaxf(a[i], mbr);
        hi[i] = fmaxf(b[i], r[i]);
    }

    const float pmx1 = fmaxf(lo[1], lo[2]);
    const float pmx3 = fmaxf(lo[3], lo[4]);
    const float mx0 = fmaxf(lo[0], pmx1);
    const float mx1 = fmaxf(pmx1, lo[3]);
    const float mx2 = fmaxf(lo[2], pmx3);
    const float mx3 = fmaxf(pmx3, lo[5]);

    const float pmn1 = fminf(hi[1], hi[2]);
    const float pmn3 = fminf(hi[3], hi[4]);
    const float mn0 = fminf(hi[0], pmn1);
    const float mn1 = fminf(pmn1, hi[3]);
    const float mn2 = fminf(hi[2], pmn3);
    const float mn3 = fminf(pmn3, hi[5]);

    const float s12 = fminf(mi[1], mi[2]);
    const float t12 = fmaxf(mi[1], mi[2]);
    const float s34 = fminf(mi[3], mi[4]);
    const float t34 = fmaxf(mi[3], mi[4]);
    const float md0 = fmaxf(s12, fminf(t12, mi[0]));
    const float md1 = fmaxf(s12, fminf(t12, mi[3]));
    const float md2 = fmaxf(s34, fminf(t34, mi[2]));
    const float md3 = fmaxf(s34, fminf(t34, mi[5]));

    float4 o;
    o.x = med3f(mx0, md0, mn0);
    o.y = med3f(mx1, md1, mn1);
    o.z = med3f(mx2, md2, mn2);
    o.w = med3f(mx3, md3, mn3);
    *reinterpret_cast<float4*>(q) = o;
}

__global__ void __launch_bounds__(256) median3x3_kernel(
    const float* __restrict__ in, float* __restrict__ out)
{
    __shared__ __align__(16) float s_slab[10][SW];

    const int plane = blockIdx.y;                    // 0..47
    const int yb    = blockIdx.x * 8;                // block's first output row
    const int tid   = threadIdx.y * 128 + threadIdx.x;
    const int x0    = threadIdx.x * 4;               // 0..508

    const float* pbase = in + (size_t)plane * (H * W);

    // ── Stage rows yb-1 .. yb+8 into the slab (coalesced, predicated). ──
    #pragma unroll
    for (int k = 0; k < 5; k++) {
        const int idx = tid + k * 256;               // 0..1279
        const int row = idx >> 7;                    // 0..9
        const int col = (idx & 127) << 2;            // 0..508
        const int gy  = yb - 1 + row;
        float4 v = make_float4(0.f, 0.f, 0.f, 0.f);
        if (gy >= 0 && gy < H)
            v = *reinterpret_cast<const float4*>(pbase + (size_t)gy * W + col);
        *reinterpret_cast<float4*>(&s_slab[row][4 + col]) = v;   // 16B aligned
    }
    if (tid < 20) {                                  // zero pads: cols -1 and 512
        const int row = tid >> 1;
        s_slab[row][(tid & 1) ? 516 : 3] = 0.0f;
    }
    __syncthreads();

    // Read 6 columns [x0-1 .. x0+4] of slab row sr — all aligned accesses.
    auto read6 = [&](float c[6], int sr) {
        const float* rp = &s_slab[sr][0];
        const float4 L = *reinterpret_cast<const float4*>(rp + x0);       // .w = col x0-1
        const float4 C = *reinterpret_cast<const float4*>(rp + 4 + x0);   // cols x0..x0+3
        c[0] = L.w;
        c[1] = C.x; c[2] = C.y; c[3] = C.z; c[4] = C.w;
        c[5] = rp[8 + x0];                                                // col x0+4
    };

    // ── Compute 4 output rows per thread from slab rows sr .. sr+5. ──
    const int sr = threadIdx.y * 4;                  // slab row of (output row - 1)
    float*    qb = out + (size_t)plane * (H * W) + (size_t)(yb + sr) * W + x0;

    float r0[6], r1[6], r2[6], r3[6], r4[6], r5[6];
    float pa[6], pb2[6];

    read6(r0, sr);
    read6(r1, sr + 1);
    read6(r2, sr + 2);
    read6(r3, sr + 3);

    #pragma unroll
    for (int i = 0; i < 6; i++) {
        pa[i]  = fminf(r1[i], r2[i]);
        pb2[i] = fmaxf(r1[i], r2[i]);
    }
    window_ins_store(pa, pb2, r0, qb);               // output row yb+sr
    window_ins_store(pa, pb2, r3, qb + W);           // output row yb+sr+1

    read6(r4, sr + 4);
    read6(r5, sr + 5);

    #pragma unroll
    for (int i = 0; i < 6; i++) {
        pa[i]  = fminf(r3[i], r4[i]);
        pb2[i] = fmaxf(r3[i], r4[i]);
    }
    window_ins_store(pa, pb2, r2, qb + 2 * W);       // output row yb+sr+2
    window_ins_store(pa, pb2, r5, qb + 3 * W);       // output row yb+sr+3
}

extern "C" void kernel_launch(void* const* d_in, const int* in_sizes, int n_in,
                              void* d_out, int out_size)
{
    const float* in  = (const float*)d_in[0];
    float*       out = (float*)d_out;

    // Block: 128 x-groups (4 px) x 2 tile-rows (256 thr), 8 output rows/block.
    dim3 block(128, 2, 1);
    dim3 grid(512 / 8, 48, 1);
    median3x3_kernel<<<grid, block>>>(in, out);
}

// round 16
// speedup vs baseline: 1.0204x; 1.0204x over previous
#include <cuda_runtime.h>
#include <cuda_bf16.h>

// 3x3 median blur, zero padding, 48 planes of 512x512 fp32.
// R13: R8's exact median network (17.5 min/max ops/output), fed from a
// shared-memory slab (R12 fixed): block stages 10 rows x (512+pads) with 5
// coalesced LDG.128/thread; per-row reads are ALIGNED LDS.128 + LDS.128 +
// LDS.32 via the layout [0..2 unused][3]=leftpad [4..515]=data [516]=rightpad,
// row stride 520 floats (16B-multiple). No halo branches, no strided LDGs.

constexpr int W  = 512;
constexpr int H  = 512;
constexpr int SW = 520;   // row stride in floats; 520*4 = 2080 B, 16B-multiple

__device__ __forceinline__ float med3f(float a, float b, float c) {
    return fmaxf(fminf(a, b), fminf(fmaxf(a, b), c));
}

// One output row: insert row r into the sorted pair (a<=b), then merge the
// 4 overlapping column-triples with shared pairwise extremes.
__device__ __forceinline__ void window_ins_store(
    const float a[6], const float b[6], const float r[6],
    float* __restrict__ q)
{
    float lo[6], mi[6], hi[6];
    #pragma unroll
    for (int i = 0; i < 6; i++) {
        const float mbr = fminf(b[i], r[i]);
        lo[i] = fminf(a[i], r[i]);
        mi[i] = fmaxf(a[i], mbr);
        hi[i] = fmaxf(b[i], r[i]);
    }

    const float pmx1 = fmaxf(lo[1], lo[2]);
    const float pmx3 = fmaxf(lo[3], lo[4]);
    const float mx0 = fmaxf(lo[0], pmx1);
    const float mx1 = fmaxf(pmx1, lo[3]);
    const float mx2 = fmaxf(lo[2], pmx3);
    const float mx3 = fmaxf(pmx3, lo[5]);

    const float pmn1 = fminf(hi[1], hi[2]);
    const float pmn3 = fminf(hi[3], hi[4]);
    const float mn0 = fminf(hi[0], pmn1);
    const float mn1 = fminf(pmn1, hi[3]);
    const float mn2 = fminf(hi[2], pmn3);
    const float mn3 = fminf(pmn3, hi[5]);

    const float s12 = fminf(mi[1], mi[2]);
    const float t12 = fmaxf(mi[1], mi[2]);
    const float s34 = fminf(mi[3], mi[4]);
    const float t34 = fmaxf(mi[3], mi[4]);
    const float md0 = fmaxf(s12, fminf(t12, mi[0]));
    const float md1 = fmaxf(s12, fminf(t12, mi[3]));
    const float md2 = fmaxf(s34, fminf(t34, mi[2]));
    const float md3 = fmaxf(s34, fminf(t34, mi[5]));

    float4 o;
    o.x = med3f(mx0, md0, mn0);
    o.y = med3f(mx1, md1, mn1);
    o.z = med3f(mx2, md2, mn2);
    o.w = med3f(mx3, md3, mn3);
    *reinterpret_cast<float4*>(q) = o;
}

__global__ void __launch_bounds__(256) median3x3_kernel(
    const float* __restrict__ in, float* __restrict__ out)
{
    __shared__ __align__(16) float s_slab[10][SW];

    const int plane = blockIdx.y;                    // 0..47
    const int yb    = blockIdx.x * 8;                // block's first output row
    const int tid   = threadIdx.y * 128 + threadIdx.x;
    const int x0    = threadIdx.x * 4;               // 0..508

    const float* pbase = in + (size_t)plane * (H * W);

    // ── Stage rows yb-1 .. yb+8 into the slab (coalesced, predicated). ──
    #pragma unroll
    for (int k = 0; k < 5; k++) {
        const int idx = tid + k * 256;               // 0..1279
        const int row = idx >> 7;                    // 0..9
        const int col = (idx & 127) << 2;            // 0..508
        const int gy  = yb - 1 + row;
        float4 v = make_float4(0.f, 0.f, 0.f, 0.f);
        if (gy >= 0 && gy < H)
            v = *reinterpret_cast<const float4*>(pbase + (size_t)gy * W + col);
        *reinterpret_cast<float4*>(&s_slab[row][4 + col]) = v;   // 16B aligned
    }
    if (tid < 20) {                                  // zero pads: cols -1 and 512
        const int row = tid >> 1;
        s_slab[row][(tid & 1) ? 516 : 3] = 0.0f;
    }
    __syncthreads();

    // Read 6 columns [x0-1 .. x0+4] of slab row sr — all aligned accesses.
    auto read6 = [&](float c[6], int sr) {
        const float* rp = &s_slab[sr][0];
        const float4 L = *reinterpret_cast<const float4*>(rp + x0);       // .w = col x0-1
        const float4 C = *reinterpret_cast<const float4*>(rp + 4 + x0);   // cols x0..x0+3
        c[0] = L.w;
        c[1] = C.x; c[2] = C.y; c[3] = C.z; c[4] = C.w;
        c[5] = rp[8 + x0];                                                // col x0+4
    };

    // ── Compute 4 output rows per thread from slab rows sr .. sr+5. ──
    const int sr = threadIdx.y * 4;                  // slab row of (output row - 1)
    float*    qb = out + (size_t)plane * (H * W) + (size_t)(yb + sr) * W + x0;

    float r0[6], r1[6], r2[6], r3[6], r4[6], r5[6];
    float pa[6], pb2[6];

    read6(r0, sr);
    read6(r1, sr + 1);
    read6(r2, sr + 2);
    read6(r3, sr + 3);

    #pragma unroll
    for (int i = 0; i < 6; i++) {
        pa[i]  = fminf(r1[i], r2[i]);
        pb2[i] = fmaxf(r1[i], r2[i]);
    }
    window_ins_store(pa, pb2, r0, qb);               // output row yb+sr
    window_ins_store(pa, pb2, r3, qb + W);           // output row yb+sr+1

    read6(r4, sr + 4);
    read6(r5, sr + 5);

    #pragma unroll
    for (int i = 0; i < 6; i++) {
        pa[i]  = fminf(r3[i], r4[i]);
        pb2[i] = fmaxf(r3[i], r4[i]);
    }
    window_ins_store(pa, pb2, r2, qb + 2 * W);       // output row yb+sr+2
    window_ins_store(pa, pb2, r5, qb + 3 * W);       // output row yb+sr+3
}

extern "C" void kernel_launch(void* const* d_in, const int* in_sizes, int n_in,
                              void* d_out, int out_size)
{
    const float* in  = (const float*)d_in[0];
    float*       out = (float*)d_out;

    // Block: 128 x-groups (4 px) x 2 tile-rows (256 thr), 8 output rows/block.
    dim3 block(128, 2, 1);
    dim3 grid(512 / 8, 48, 1);
    median3x3_kernel<<<grid, block>>>(in, out);
}

// round 17
// speedup vs baseline: 1.0990x; 1.0770x over previous
#include <cuda_runtime.h>
#include <cuda_bf16.h>

// 3x3 median blur, zero padding, 48 planes of 512x512 fp32.
// R14: R8's exact median network (shared sorted row-pairs + shared horizontal
// extremes, 17.5 min/max ops per output) in a rolling TILE_H=8 structure:
// 4-row rotating register buffer, each stage sorts one row-pair, emits two
// output rows, then refills the two expired buffers. Loads interleave with
// compute (R6's winning structural property) and drop to 1.25 rows/output.

constexpr int W = 512;
constexpr int H = 512;

__device__ __forceinline__ float med3f(float a, float b, float c) {
    return fmaxf(fminf(a, b), fminf(fmaxf(a, b), c));
}

// Load 6 columns [x0-1 .. x0+4] of row yy into c (zeros outside the plane).
__device__ __forceinline__ void load6(float c[6], const float* __restrict__ pb,
                                      int yy, int x0) {
    if (yy < 0 || yy >= H) {
        #pragma unroll
        for (int i = 0; i < 6; i++) c[i] = 0.0f;
        return;
    }
    const float* row = pb + (size_t)yy * W;
    const float4 v = *reinterpret_cast<const float4*>(row + x0);
    c[1] = v.x; c[2] = v.y; c[3] = v.z; c[4] = v.w;
    c[0] = (x0 > 0)     ? __ldg(row + x0 - 1) : 0.0f;
    c[5] = (x0 + 4 < W) ? __ldg(row + x0 + 4) : 0.0f;
}

// One output row: insert row r into the sorted pair (a<=b), then merge the
// 4 overlapping column-triples with shared pairwise extremes.
__device__ __forceinline__ void window_ins_store(
    const float a[6], const float b[6], const float r[6],
    float* __restrict__ q)
{
    float lo[6], mi[6], hi[6];
    #pragma unroll
    for (int i = 0; i < 6; i++) {
        const float mbr = fminf(b[i], r[i]);
        lo[i] = fminf(a[i], r[i]);
        mi[i] = fmaxf(a[i], mbr);
        hi[i] = fmaxf(b[i], r[i]);
    }

    const float pmx1 = fmaxf(lo[1], lo[2]);
    const float pmx3 = fmaxf(lo[3], lo[4]);
    const float mx0 = fmaxf(lo[0], pmx1);
    const float mx1 = fmaxf(pmx1, lo[3]);
    const float mx2 = fmaxf(lo[2], pmx3);
    const float mx3 = fmaxf(pmx3, lo[5]);

    const float pmn1 = fminf(hi[1], hi[2]);
    const float pmn3 = fminf(hi[3], hi[4]);
    const float mn0 = fminf(hi[0], pmn1);
    const float mn1 = fminf(pmn1, hi[3]);
    const float mn2 = fminf(hi[2], pmn3);
    const float mn3 = fminf(pmn3, hi[5]);

    const float s12 = fminf(mi[1], mi[2]);
    const float t12 = fmaxf(mi[1], mi[2]);
    const float s34 = fminf(mi[3], mi[4]);
    const float t34 = fmaxf(mi[3], mi[4]);
    const float md0 = fmaxf(s12, fminf(t12, mi[0]));
    const float md1 = fmaxf(s12, fminf(t12, mi[3]));
    const float md2 = fmaxf(s34, fminf(t34, mi[2]));
    const float md3 = fmaxf(s34, fminf(t34, mi[5]));

    float4 o;
    o.x = med3f(mx0, md0, mn0);
    o.y = med3f(mx1, md1, mn1);
    o.z = med3f(mx2, md2, mn2);
    o.w = med3f(mx3, md3, mn3);
    *reinterpret_cast<float4*>(q) = o;
}

__global__ void __launch_bounds__(256) median3x3_kernel(
    const float* __restrict__ in, float* __restrict__ out)
{
    const int plane = blockIdx.y;                               // 0..47
    const int x0    = threadIdx.x * 4;                          // 0..508
    const int y0    = (blockIdx.x * 2 + threadIdx.y) * 8;       // top output row

    const float* pbase = in  + (size_t)plane * (H * W);
    float*       qb    = out + (size_t)plane * (H * W) + (size_t)y0 * W + x0;

    // Rotating 4-row buffer: input row t lives in rb[(t+1) & 3] (t from -1).
    float rb[4][6];
    float pa[6], pb2[6];

    load6(rb[0], pbase, y0 - 1, x0);
    load6(rb[1], pbase, y0,     x0);
    load6(rb[2], pbase, y0 + 1, x0);
    load6(rb[3], pbase, y0 + 2, x0);

    #pragma unroll
    for (int s = 0; s < 4; s++) {
        const int iprev = (2 * s)     & 3;   // row 2s-1
        const int ia    = (2 * s + 1) & 3;   // row 2s
        const int ib    = (2 * s + 2) & 3;   // row 2s+1
        const int inx   = (2 * s + 3) & 3;   // row 2s+2

        // Shared sorted pair of rows (2s, 2s+1).
        #pragma unroll
        for (int i = 0; i < 6; i++) {
            pa[i]  = fminf(rb[ia][i], rb[ib][i]);
            pb2[i] = fmaxf(rb[ia][i], rb[ib][i]);
        }
        window_ins_store(pa, pb2, rb[iprev], qb + (size_t)(2 * s) * W);
        window_ins_store(pa, pb2, rb[inx],   qb + (size_t)(2 * s + 1) * W);

        // Refill the two expired buffers with rows 2s+3, 2s+4.
        if (s < 3) {
            load6(rb[iprev], pbase, y0 + 2 * s + 3, x0);  // -> slot (2s+4)&3
            load6(rb[ia],    pbase, y0 + 2 * s + 4, x0);  // -> slot (2s+5)&3
        }
    }
}

extern "C" void kernel_launch(void* const* d_in, const int* in_sizes, int n_in,
                              void* d_out, int out_size)
{
    const float* in  = (const float*)d_in[0];
    float*       out = (float*)d_out;

    // Block: 128 x-groups (4 px) x 2 thread-rows (256 thr); 8 rows/thread.
    dim3 block(128, 2, 1);
    dim3 grid(512 / 16, 48, 1);
    median3x3_kernel<<<grid, block>>>(in, out);
}